// round 2
// baseline (speedup 1.0000x reference)
#include <cuda_runtime.h>
#include <math.h>

// ---------------------------------------------------------------------------
// EncoderLayer sparse U-Net (B=4, D=64, C=16, NS=4), dense-emulated with
// active-site compaction. fp32 throughout.
// Output: [hidden (4*8192) | out (4*64^3)] = 1,081,344 floats.
// ---------------------------------------------------------------------------

#define CDIV(a,b) (((a)+(b)-1)/(b))

#define Bn 4
#define Cn 16
#define GBN 128

#define NS0 (4*64*64*64)   // 1048576 sites at 64^3
#define NS1 (4*32*32*32)   // 131072
#define NS2 (4*16*16*16)   // 16384
#define NS3 (4*8*8*8)      // 2048
#define LXC (Bn*Cn*64*64*64) // 16777216 floats (full 16-ch 64^3 tensor)

// float scratch arena offsets
#define OFF_XA 0L
#define OFF_XB (OFF_XA + LXC)
#define OFF_M0 (OFF_XB + LXC)
#define OFF_M1 (OFF_M0 + NS0)
#define OFF_M2 (OFF_M1 + NS1)
#define OFF_M3 (OFF_M2 + NS2)
#define MEM_TOTAL (OFF_M3 + NS3)

__device__ float  g_mem[MEM_TOTAL];
__device__ int    g_list[NS0 + NS1 + NS2 + NS3];
#define LOFF0 0
#define LOFF1 (NS0)
#define LOFF2 (NS0+NS1)
#define LOFF3 (NS0+NS1+NS2)
__device__ int    g_cnt[4];
__device__ double g_psum[GBN*Cn];
__device__ double g_psq [GBN*Cn];
__device__ double g_pcnt[GBN];
__device__ float  g_A[Cn];
__device__ float  g_Bb[Cn];

// ------------------------------- elementwise -------------------------------

__global__ void k_zero(long off, int n) {
    float* p = g_mem + off;
    for (int i = blockIdx.x*blockDim.x + threadIdx.x; i < n; i += gridDim.x*blockDim.x)
        p[i] = 0.f;
}

__global__ void k_reset(int idx) { if (threadIdx.x == 0) g_cnt[idx] = 0; }

__global__ void k_scatter(const float* __restrict__ data, const int* __restrict__ cid, int n) {
    int i = blockIdx.x*blockDim.x + threadIdx.x;
    if (i >= n) return;
    int z = (int)data[i*5+0];
    int y = (int)data[i*5+1];
    int x = (int)data[i*5+2];
    int b = cid[i];
    atomicAdd(&g_mem[OFF_XA + ((((long)b*64 + z)*64 + y)*64 + x)], 1.0f);
}

// mask[i] = src[i] > 0 ; append active sites to list
__global__ void k_mask_list(long srcoff, long moff, int loff, int cidx, int n) {
    int i = blockIdx.x*blockDim.x + threadIdx.x;
    if (i >= n) return;
    bool a = g_mem[srcoff + i] > 0.f;
    g_mem[moff + i] = a ? 1.f : 0.f;
    if (a) {
        int p = atomicAdd(&g_cnt[cidx], 1);
        g_list[loff + p] = i;
    }
}

// out mask at size S from in mask at size 2S (2x2x2 any-active)
__global__ void k_downmask(long inoff, long outoff, int S) {
    int n = Bn*S*S*S;
    int i = blockIdx.x*blockDim.x + threadIdx.x;
    if (i >= n) return;
    int S2 = S*S, S3 = S2*S;
    int b = i / S3; int r = i - b*S3;
    int z = r / S2; r -= z*S2;
    int y = r / S;  int x = r - y*S;
    int Si = 2*S, Si2 = Si*Si, Si3 = Si2*Si;
    const float* mi = g_mem + inoff + (long)b*Si3;
    float any = 0.f;
#pragma unroll
    for (int a = 0; a < 2; a++)
#pragma unroll
        for (int bb = 0; bb < 2; bb++)
#pragma unroll
            for (int c = 0; c < 2; c++) {
                float v = mi[(2*z+a)*Si2 + (2*y+bb)*Si + (2*x+c)];
                any = fmaxf(any, v);
            }
    g_mem[outoff + i] = any > 0.f ? 1.f : 0.f;
}

// m[i] = m[i] * (x[b, ch0, site] > 0)
__global__ void k_sparsify(long moff, long xoff, int S3) {
    int n = Bn*S3;
    int i = blockIdx.x*blockDim.x + threadIdx.x;
    if (i >= n) return;
    int b = i / S3; int sp = i - b*S3;
    float v = g_mem[xoff + (long)(b*Cn)*S3 + sp];
    float m = g_mem[moff + i];
    g_mem[moff + i] = (m > 0.f && v > 0.f) ? 1.f : 0.f;
}

// x *= mask (dense over all channels)
__global__ void k_maskmul(long xoff, long moff, int S3) {
    int n = Bn*Cn*S3;
    for (int i = blockIdx.x*blockDim.x + threadIdx.x; i < n; i += gridDim.x*blockDim.x) {
        int cs = i / S3; int sp = i - cs*S3;
        int b = cs / Cn;
        g_mem[xoff + i] *= g_mem[moff + b*S3 + sp];
    }
}

__global__ void k_copy(float* __restrict__ dst, long srcoff, int n) {
    for (int i = blockIdx.x*blockDim.x + threadIdx.x; i < n; i += gridDim.x*blockDim.x)
        dst[i] = g_mem[srcoff + i];
}

// ------------------------------- BatchNorm ---------------------------------

__global__ void k_bn_part(long xoff, long moff, int S3) {
    const float* x = g_mem + xoff;
    const float* m = g_mem + moff;
    int c = blockIdx.y;
    int total = Bn*S3;
    double s = 0.0, q = 0.0, n = 0.0;
    for (int i = blockIdx.x*blockDim.x + threadIdx.x; i < total; i += gridDim.x*blockDim.x) {
        float mk = m[i];
        if (mk != 0.f) {
            int b = i / S3; int sp = i - b*S3;
            float v = x[(b*Cn + c)*S3 + sp];
            s += (double)v;
            q += (double)v * (double)v;
            n += 1.0;
        }
    }
    __shared__ double sh[256];
    int t = threadIdx.x;
    sh[t] = s; __syncthreads();
    for (int o = 128; o > 0; o >>= 1) { if (t < o) sh[t] += sh[t+o]; __syncthreads(); }
    if (t == 0) g_psum[c*gridDim.x + blockIdx.x] = sh[0];
    __syncthreads();
    sh[t] = q; __syncthreads();
    for (int o = 128; o > 0; o >>= 1) { if (t < o) sh[t] += sh[t+o]; __syncthreads(); }
    if (t == 0) g_psq[c*gridDim.x + blockIdx.x] = sh[0];
    if (c == 0) {
        __syncthreads();
        sh[t] = n; __syncthreads();
        for (int o = 128; o > 0; o >>= 1) { if (t < o) sh[t] += sh[t+o]; __syncthreads(); }
        if (t == 0) g_pcnt[blockIdx.x] = sh[0];
    }
}

__global__ void k_bn_fin(const float* __restrict__ gamma, const float* __restrict__ beta) {
    __shared__ double ncnt;
    if (threadIdx.x == 0) {
        double n = 0.0;
        for (int g = 0; g < GBN; g++) n += g_pcnt[g];
        ncnt = n < 1.0 ? 1.0 : n;
    }
    __syncthreads();
    int c = threadIdx.x;
    if (c < Cn) {
        double s = 0.0, q = 0.0;
        for (int g = 0; g < GBN; g++) { s += g_psum[c*GBN + g]; q += g_psq[c*GBN + g]; }
        double mean = s / ncnt;
        double var  = q / ncnt - mean*mean;
        double inv  = 1.0 / sqrt(var + 1e-4);
        double A    = (double)gamma[c] * inv;
        g_A[c]  = (float)A;
        g_Bb[c] = (float)((double)beta[c] - mean*A);
    }
}

// x = relu(x*A + B) * mask  (LEAK=0)
__global__ void k_bn_apply(long xoff, long moff, int S3) {
    int n = Bn*Cn*S3;
    for (int i = blockIdx.x*blockDim.x + threadIdx.x; i < n; i += gridDim.x*blockDim.x) {
        int cs = i / S3; int sp = i - cs*S3;
        int b = cs / Cn; int c = cs - b*Cn;
        float mk = g_mem[moff + b*S3 + sp];
        float v  = g_mem[xoff + i] * g_A[c] + g_Bb[c];
        g_mem[xoff + i] = (v > 0.f ? v : 0.f) * mk;
    }
}

// ------------------------------- convolutions ------------------------------

// k=3, pad=1 submanifold conv over active list
template<int CIN, int COUT>
__global__ void k_conv3(long inoff, long outoff, const float* __restrict__ w,
                        int loff, int cidx, int S) {
    if (blockIdx.x * blockDim.x >= g_cnt[cidx]) return;
    __shared__ __align__(16) float sw[27*CIN*COUT];
    for (int i = threadIdx.x; i < 27*CIN*COUT; i += blockDim.x) sw[i] = w[i];
    __syncthreads();
    int idx = blockIdx.x*blockDim.x + threadIdx.x;
    if (idx >= g_cnt[cidx]) return;
    int site = g_list[loff + idx];
    const float* in = g_mem + inoff;
    float* out = g_mem + outoff;
    int S2 = S*S, S3 = S2*S;
    int b = site / S3; int r = site - b*S3;
    int z = r / S2; r -= z*S2;
    int y = r / S;  int x = r - y*S;
    float acc[COUT];
#pragma unroll
    for (int co = 0; co < COUT; co++) acc[co] = 0.f;
#pragma unroll 1
    for (int dz = 0; dz < 3; dz++) {
        int zz = z + dz - 1; if ((unsigned)zz >= (unsigned)S) continue;
#pragma unroll 1
        for (int dy = 0; dy < 3; dy++) {
            int yy = y + dy - 1; if ((unsigned)yy >= (unsigned)S) continue;
#pragma unroll
            for (int dx = 0; dx < 3; dx++) {
                int xx = x + dx - 1; if ((unsigned)xx >= (unsigned)S) continue;
                const float* ip = in + (b*CIN)*S3 + zz*S2 + yy*S + xx;
                const float* wp = sw + (((dz*3 + dy)*3 + dx)*CIN)*COUT;
#pragma unroll
                for (int ci = 0; ci < CIN; ci++) {
                    float v = ip[ci*S3];
                    const float* wc = wp + ci*COUT;
#pragma unroll
                    for (int co = 0; co < COUT; co++) acc[co] += v * wc[co];
                }
            }
        }
    }
    float* op = out + (b*COUT)*S3 + z*S2 + y*S + x;
#pragma unroll
    for (int co = 0; co < COUT; co++) op[co*S3] = acc[co];
}

// k=4, pad=(1,2) submanifold conv (16->16); weights streamed by dz-slice (16KB smem)
__global__ void k_conv4(long inoff, long outoff, const float* __restrict__ w,
                        int loff, int cidx, int S) {
    if (blockIdx.x * blockDim.x >= g_cnt[cidx]) return;
    __shared__ __align__(16) float sw[16*Cn*Cn]; // one dz slice: 4*4*16*16 = 4096 floats
    int idx = blockIdx.x*blockDim.x + threadIdx.x;
    bool act = idx < g_cnt[cidx];
    int site = act ? g_list[loff + idx] : 0;
    const float* in = g_mem + inoff;
    float* out = g_mem + outoff;
    int S2 = S*S, S3 = S2*S;
    int b = site / S3; int r = site - b*S3;
    int z = r / S2; r -= z*S2;
    int y = r / S;  int x = r - y*S;
    float acc[Cn];
#pragma unroll
    for (int co = 0; co < Cn; co++) acc[co] = 0.f;
#pragma unroll 1
    for (int dz = 0; dz < 4; dz++) {
        __syncthreads();
        for (int i = threadIdx.x; i < 16*Cn*Cn; i += blockDim.x) sw[i] = w[dz*16*Cn*Cn + i];
        __syncthreads();
        int zz = z + dz - 1;
        if (act && (unsigned)zz < (unsigned)S) {
#pragma unroll 1
            for (int dy = 0; dy < 4; dy++) {
                int yy = y + dy - 1; if ((unsigned)yy >= (unsigned)S) continue;
#pragma unroll
                for (int dx = 0; dx < 4; dx++) {
                    int xx = x + dx - 1; if ((unsigned)xx >= (unsigned)S) continue;
                    const float* ip = in + (b*Cn)*S3 + zz*S2 + yy*S + xx;
                    const float* wp = sw + ((dy*4 + dx)*Cn)*Cn;
#pragma unroll
                    for (int ci = 0; ci < Cn; ci++) {
                        float v = ip[ci*S3];
                        const float* wc = wp + ci*Cn;
#pragma unroll
                        for (int co = 0; co < Cn; co++) acc[co] += v * wc[co];
                    }
                }
            }
        }
    }
    if (act) {
        float* op = out + (b*Cn)*S3 + z*S2 + y*S + x;
#pragma unroll
        for (int co = 0; co < Cn; co++) op[co*S3] = acc[co];
    }
}

// strided k=2 s=2 downsampling conv; S = output size, input at 2S, list on new mask
__global__ void k_down(long inoff, long outoff, const float* __restrict__ w,
                       int loff, int cidx, int S) {
    if (blockIdx.x * blockDim.x >= g_cnt[cidx]) return;
    __shared__ __align__(16) float sw[8*Cn*Cn];
    for (int i = threadIdx.x; i < 8*Cn*Cn; i += blockDim.x) sw[i] = w[i];
    __syncthreads();
    int idx = blockIdx.x*blockDim.x + threadIdx.x;
    if (idx >= g_cnt[cidx]) return;
    int site = g_list[loff + idx];
    const float* in = g_mem + inoff;
    float* out = g_mem + outoff;
    int S2 = S*S, S3 = S2*S;
    int b = site / S3; int r = site - b*S3;
    int z = r / S2; r -= z*S2;
    int y = r / S;  int x = r - y*S;
    int Si = 2*S, Si2 = Si*Si, Si3 = Si2*Si;
    float acc[Cn];
#pragma unroll
    for (int co = 0; co < Cn; co++) acc[co] = 0.f;
#pragma unroll 1
    for (int a = 0; a < 2; a++)
#pragma unroll 1
        for (int bb = 0; bb < 2; bb++)
#pragma unroll
            for (int c = 0; c < 2; c++) {
                const float* ip = in + (b*Cn)*Si3 + (2*z+a)*Si2 + (2*y+bb)*Si + (2*x+c);
                const float* wp = sw + (((a*2 + bb)*2 + c)*Cn)*Cn;
#pragma unroll
                for (int ci = 0; ci < Cn; ci++) {
                    float v = ip[ci*Si3];
                    const float* wc = wp + ci*Cn;
#pragma unroll
                    for (int co = 0; co < Cn; co++) acc[co] += v * wc[co];
                }
            }
    float* op = out + (b*Cn)*S3 + z*S2 + y*S + x;
#pragma unroll
    for (int co = 0; co < Cn; co++) op[co*S3] = acc[co];
}

// conv_transpose k=2 s=2 VALID: out[2m+a] uses w[1-a]; S = output size, input at S/2
__global__ void k_up(long inoff, long outoff, const float* __restrict__ w,
                     int loff, int cidx, int S) {
    if (blockIdx.x * blockDim.x >= g_cnt[cidx]) return;
    __shared__ __align__(16) float sw[8*Cn*Cn];
    for (int i = threadIdx.x; i < 8*Cn*Cn; i += blockDim.x) sw[i] = w[i];
    __syncthreads();
    int idx = blockIdx.x*blockDim.x + threadIdx.x;
    if (idx >= g_cnt[cidx]) return;
    int site = g_list[loff + idx];
    const float* in = g_mem + inoff;
    float* out = g_mem + outoff;
    int S2 = S*S, S3 = S2*S;
    int b = site / S3; int r = site - b*S3;
    int z = r / S2; r -= z*S2;
    int y = r / S;  int x = r - y*S;
    int Sh = S >> 1, Sh2 = Sh*Sh, Sh3 = Sh2*Sh;
    int tz = 1 - (z & 1), ty = 1 - (y & 1), tx = 1 - (x & 1);
    const float* wp = sw + (((tz*2 + ty)*2 + tx)*Cn)*Cn;
    const float* ip = in + (b*Cn)*Sh3 + (z >> 1)*Sh2 + (y >> 1)*Sh + (x >> 1);
    float acc[Cn];
#pragma unroll
    for (int co = 0; co < Cn; co++) acc[co] = 0.f;
#pragma unroll
    for (int ci = 0; ci < Cn; ci++) {
        float v = ip[ci*Sh3];
        const float* wc = wp + ci*Cn;
#pragma unroll
        for (int co = 0; co < Cn; co++) acc[co] += v * wc[co];
    }
    float* op = out + (b*Cn)*S3 + z*S2 + y*S + x;
#pragma unroll
    for (int co = 0; co < Cn; co++) op[co*S3] = acc[co];
}

// ------------------------------- host --------------------------------------

static void bn_stage(long xoff, long moff, int S3, const float* gamma, const float* beta) {
    dim3 gp(GBN, Cn);
    k_bn_part<<<gp, 256>>>(xoff, moff, S3);
    k_bn_fin<<<1, 32>>>(gamma, beta);
    int total = Bn*Cn*S3;
    int g = CDIV(total, 256); if (g > 8192) g = 8192;
    k_bn_apply<<<g, 256>>>(xoff, moff, S3);
}

static void build_list(long srcoff, long moff, int loff, int cidx, int n) {
    k_reset<<<1, 1>>>(cidx);
    k_mask_list<<<CDIV(n, 256), 256>>>(srcoff, moff, loff, cidx, n);
}

extern "C" void kernel_launch(void* const* d_in, const int* in_sizes, int n_in,
                              void* d_out, int out_size) {
    const float* data      = (const float*)d_in[0];
    const int*   cid       = (const int*)  d_in[1];
    const float* w_prep    = (const float*)d_in[2];
    const float* enc_gamma = (const float*)d_in[3];
    const float* enc_beta  = (const float*)d_in[4];
    const float* enc_wsub  = (const float*)d_in[5];
    const float* enc_wdown = (const float*)d_in[6];
    const float* dec_gamma = (const float*)d_in[7];
    const float* dec_beta  = (const float*)d_in[8];
    const float* dec_wup   = (const float*)d_in[9];
    const float* dec_wsub3 = (const float*)d_in[10];
    const float* dec_wsub4 = (const float*)d_in[11];
    const float* w_out     = (const float*)d_in[12];
    float* outp = (float*)d_out;
    int npts = in_sizes[0] / 5;
    const int T = 256;
    (void)n_in; (void)out_size;

    // ---- input scatter (counts) + level-0 mask/list ----
    k_zero<<<2048, T>>>(OFF_XA, NS0);
    k_scatter<<<CDIV(npts, T), T>>>(data, cid, npts);
    build_list(OFF_XA, OFF_M0, LOFF0, 0, NS0);

    // ---- prepare: SubmanifoldConv(1->16, k3) ----
    k_zero<<<8192, T>>>(OFF_XB, LXC);
    k_conv3<1, Cn><<<CDIV(NS0, T), T>>>(OFF_XA, OFF_XB, w_prep, LOFF0, 0, 64);

    // ---- encoder stage 0 (64^3 -> 32^3) ----
    bn_stage(OFF_XB, OFF_M0, 64*64*64, enc_gamma + 0, enc_beta + 0);
    k_zero<<<8192, T>>>(OFF_XA, LXC);
    k_conv3<Cn, Cn><<<CDIV(NS0, T), T>>>(OFF_XB, OFF_XA, enc_wsub + 0, LOFF0, 0, 64);
    k_downmask<<<CDIV(NS1, T), T>>>(OFF_M0, OFF_M1, 32);
    build_list(OFF_M1, OFF_M1, LOFF1, 1, NS1);
    k_zero<<<2048, T>>>(OFF_XB, Cn*NS1);
    k_down<<<CDIV(NS1, T), T>>>(OFF_XA, OFF_XB, enc_wdown + 0, LOFF1, 1, 32);

    // ---- encoder stage 1 (32^3 -> 16^3) ----
    bn_stage(OFF_XB, OFF_M1, 32*32*32, enc_gamma + 16, enc_beta + 16);
    k_zero<<<2048, T>>>(OFF_XA, Cn*NS1);
    k_conv3<Cn, Cn><<<CDIV(NS1, T), T>>>(OFF_XB, OFF_XA, enc_wsub + 6912, LOFF1, 1, 32);
    k_downmask<<<CDIV(NS2, T), T>>>(OFF_M1, OFF_M2, 16);
    build_list(OFF_M2, OFF_M2, LOFF2, 2, NS2);
    k_zero<<<512, T>>>(OFF_XB, Cn*NS2);
    k_down<<<CDIV(NS2, T), T>>>(OFF_XA, OFF_XB, enc_wdown + 2048, LOFF2, 2, 16);

    // ---- encoder stage 2 (16^3 -> 8^3) ----
    bn_stage(OFF_XB, OFF_M2, 16*16*16, enc_gamma + 32, enc_beta + 32);
    k_zero<<<512, T>>>(OFF_XA, Cn*NS2);
    k_conv3<Cn, Cn><<<CDIV(NS2, T), T>>>(OFF_XB, OFF_XA, enc_wsub + 13824, LOFF2, 2, 16);
    k_downmask<<<CDIV(NS3, T), T>>>(OFF_M2, OFF_M3, 8);
    build_list(OFF_M3, OFF_M3, LOFF3, 3, NS3);
    k_zero<<<128, T>>>(OFF_XB, Cn*NS3);
    k_down<<<CDIV(NS3, T), T>>>(OFF_XA, OFF_XB, enc_wdown + 4096, LOFF3, 3, 8);

    // ---- hidden output (x3 flattened = NCDHW layout) ----
    k_copy<<<CDIV(Cn*NS3, T), T>>>(outp, OFF_XB, Cn*NS3);

    // ---- decoder stage j=0 (lvl 2: 8^3 -> 16^3) ----
    bn_stage(OFF_XB, OFF_M3, 8*8*8, dec_gamma + 0, dec_beta + 0);
    k_zero<<<512, T>>>(OFF_XA, Cn*NS2);
    k_up<<<CDIV(NS2, T), T>>>(OFF_XB, OFF_XA, dec_wup + 0, LOFF2, 2, 16);
    k_zero<<<512, T>>>(OFF_XB, Cn*NS2);
    k_conv3<Cn, Cn><<<CDIV(NS2, T), T>>>(OFF_XA, OFF_XB, dec_wsub3 + 0, LOFF2, 2, 16);
    k_sparsify<<<CDIV(NS2, T), T>>>(OFF_M2, OFF_XB, 16*16*16);
    k_maskmul<<<CDIV(Cn*NS2, T), T>>>(OFF_XB, OFF_M2, 16*16*16);
    build_list(OFF_M2, OFF_M2, LOFF2, 2, NS2);
    k_zero<<<512, T>>>(OFF_XA, Cn*NS2);
    k_conv4<<<CDIV(NS2, T), T>>>(OFF_XB, OFF_XA, dec_wsub4 + 0, LOFF2, 2, 16);

    // ---- decoder stage j=1 (lvl 1: 16^3 -> 32^3) ----
    bn_stage(OFF_XA, OFF_M2, 16*16*16, dec_gamma + 16, dec_beta + 16);
    k_zero<<<2048, T>>>(OFF_XB, Cn*NS1);
    k_up<<<CDIV(NS1, T), T>>>(OFF_XA, OFF_XB, dec_wup + 2048, LOFF1, 1, 32);
    k_zero<<<2048, T>>>(OFF_XA, Cn*NS1);
    k_conv3<Cn, Cn><<<CDIV(NS1, T), T>>>(OFF_XB, OFF_XA, dec_wsub3 + 6912, LOFF1, 1, 32);
    k_sparsify<<<CDIV(NS1, T), T>>>(OFF_M1, OFF_XA, 32*32*32);
    k_maskmul<<<CDIV(Cn*NS1, T), T>>>(OFF_XA, OFF_M1, 32*32*32);
    build_list(OFF_M1, OFF_M1, LOFF1, 1, NS1);
    k_zero<<<2048, T>>>(OFF_XB, Cn*NS1);
    k_conv4<<<CDIV(NS1, T), T>>>(OFF_XA, OFF_XB, dec_wsub4 + 16384, LOFF1, 1, 32);

    // ---- decoder stage j=2 (lvl 0: 32^3 -> 64^3) ----
    bn_stage(OFF_XB, OFF_M1, 32*32*32, dec_gamma + 32, dec_beta + 32);
    k_zero<<<8192, T>>>(OFF_XA, LXC);
    k_up<<<CDIV(NS0, T), T>>>(OFF_XB, OFF_XA, dec_wup + 4096, LOFF0, 0, 64);
    k_zero<<<8192, T>>>(OFF_XB, LXC);
    k_conv3<Cn, Cn><<<CDIV(NS0, T), T>>>(OFF_XA, OFF_XB, dec_wsub3 + 13824, LOFF0, 0, 64);
    k_sparsify<<<CDIV(NS0, T), T>>>(OFF_M0, OFF_XB, 64*64*64);
    k_maskmul<<<8192, T>>>(OFF_XB, OFF_M0, 64*64*64);
    build_list(OFF_M0, OFF_M0, LOFF0, 0, NS0);
    k_zero<<<8192, T>>>(OFF_XA, LXC);
    k_conv4<<<CDIV(NS0, T), T>>>(OFF_XB, OFF_XA, dec_wsub4 + 32768, LOFF0, 0, 64);

    // ---- output conv (16->1, k3) ----
    k_zero<<<2048, T>>>(OFF_XB, NS0);
    k_conv3<Cn, 1><<<CDIV(NS0, T), T>>>(OFF_XA, OFF_XB, w_out, LOFF0, 0, 64);
    k_copy<<<4096, T>>>(outp + Cn*NS3, OFF_XB, NS0);
}

// round 3
// speedup vs baseline: 1.6423x; 1.6423x over previous
#include <cuda_runtime.h>
#include <math.h>

#define CDIV(a,b) (((a)+(b)-1)/(b))
#define Bn 4
#define Cn 16
#define GBN 128

#define NS0 (4*64*64*64)
#define NS1 (4*32*32*32)
#define NS2 (4*16*16*16)
#define NS3 (4*8*8*8)
#define LXC (Bn*Cn*64*64*64)

#define OFF_XA 0L
#define OFF_XB (OFF_XA + LXC)
#define OFF_M0 (OFF_XB + LXC)
#define OFF_M1 (OFF_M0 + NS0)
#define OFF_M2 (OFF_M1 + NS1)
#define OFF_M3 (OFF_M2 + NS2)
#define MEM_TOTAL (OFF_M3 + NS3)

__device__ __align__(16) float g_mem[MEM_TOTAL];
__device__ int    g_list[NS0 + NS1 + NS2 + NS3];
#define LOFF0 0
#define LOFF1 (NS0)
#define LOFF2 (NS0+NS1)
#define LOFF3 (NS0+NS1+NS2)
__device__ int    g_cnt[4];
__device__ int    g_blk[4096];
__device__ double g_psum[Cn*GBN];
__device__ double g_psq [Cn*GBN];
__device__ float  g_A[Cn];
__device__ float  g_Bb[Cn];

typedef unsigned long long ull;

__device__ __forceinline__ ull pack2(float v) {
    ull r; asm("mov.b64 %0, {%1, %1};" : "=l"(r) : "f"(v)); return r;
}
__device__ __forceinline__ void fma2(ull& a, ull v, ull w) {
    asm("fma.rn.f32x2 %0, %1, %2, %0;" : "+l"(a) : "l"(v), "l"(w));
}
__device__ __forceinline__ float2 unpack2(ull a) {
    float2 f; asm("mov.b64 {%0, %1}, %2;" : "=f"(f.x), "=f"(f.y) : "l"(a)); return f;
}

#define LOAD16(dst, ptr) do { const float4* _p = (const float4*)(ptr); float4 _v; \
    _v=_p[0]; dst[0]=_v.x; dst[1]=_v.y; dst[2]=_v.z; dst[3]=_v.w; \
    _v=_p[1]; dst[4]=_v.x; dst[5]=_v.y; dst[6]=_v.z; dst[7]=_v.w; \
    _v=_p[2]; dst[8]=_v.x; dst[9]=_v.y; dst[10]=_v.z; dst[11]=_v.w; \
    _v=_p[3]; dst[12]=_v.x; dst[13]=_v.y; dst[14]=_v.z; dst[15]=_v.w; } while(0)

#define STORE16(ptr, a) do { float4* _o = (float4*)(ptr); float2 _f; float4 _q; \
    _f=unpack2(a[0]); _q.x=_f.x; _q.y=_f.y; _f=unpack2(a[1]); _q.z=_f.x; _q.w=_f.y; _o[0]=_q; \
    _f=unpack2(a[2]); _q.x=_f.x; _q.y=_f.y; _f=unpack2(a[3]); _q.z=_f.x; _q.w=_f.y; _o[1]=_q; \
    _f=unpack2(a[4]); _q.x=_f.x; _q.y=_f.y; _f=unpack2(a[5]); _q.z=_f.x; _q.w=_f.y; _o[2]=_q; \
    _f=unpack2(a[6]); _q.x=_f.x; _q.y=_f.y; _f=unpack2(a[7]); _q.z=_f.x; _q.w=_f.y; _o[3]=_q; } while(0)

// ------------------------------- elementwise -------------------------------

__global__ void k_zero4(long off, int n4) {
    float4* p = (float4*)(g_mem + off);
    float4 z = make_float4(0.f,0.f,0.f,0.f);
    for (int i = blockIdx.x*blockDim.x + threadIdx.x; i < n4; i += gridDim.x*blockDim.x)
        p[i] = z;
}
__global__ void k_zerop4(float* p, int n4) {
    float4* q = (float4*)p;
    float4 z = make_float4(0.f,0.f,0.f,0.f);
    for (int i = blockIdx.x*blockDim.x + threadIdx.x; i < n4; i += gridDim.x*blockDim.x)
        q[i] = z;
}

__global__ void k_scatter(const float* __restrict__ data, const int* __restrict__ cid, int n) {
    int i = blockIdx.x*blockDim.x + threadIdx.x;
    if (i >= n) return;
    int z = (int)data[i*5+0];
    int y = (int)data[i*5+1];
    int x = (int)data[i*5+2];
    int b = cid[i];
    atomicAdd(&g_mem[OFF_XA + ((((long)b*64 + z)*64 + y)*64 + x)], 1.0f);
}

// ------------------------- ordered list compaction -------------------------

__global__ void k_count(long srcoff, int n) {
    int i = blockIdx.x*256 + threadIdx.x;
    bool a = (i < n) && (g_mem[srcoff + i] > 0.f);
    unsigned bal = __ballot_sync(0xffffffffu, a);
    __shared__ int ws[8];
    if ((threadIdx.x & 31) == 0) ws[threadIdx.x >> 5] = __popc(bal);
    __syncthreads();
    if (threadIdx.x == 0) {
        int s = 0;
        #pragma unroll
        for (int j = 0; j < 8; j++) s += ws[j];
        g_blk[blockIdx.x] = s;
    }
}

__global__ void k_scan(int G, int cidx) {
    __shared__ int sh[32];
    int t = threadIdx.x;
    int base = t*4;
    int v0=0,v1=0,v2=0,v3=0;
    if (base+0 < G) v0 = g_blk[base+0];
    if (base+1 < G) v1 = g_blk[base+1];
    if (base+2 < G) v2 = g_blk[base+2];
    if (base+3 < G) v3 = g_blk[base+3];
    int sum = v0+v1+v2+v3;
    int lane = t & 31, wid = t >> 5;
    int x = sum;
    #pragma unroll
    for (int o = 1; o < 32; o <<= 1) {
        int y = __shfl_up_sync(0xffffffffu, x, o);
        if (lane >= o) x += y;
    }
    if (lane == 31) sh[wid] = x;
    __syncthreads();
    if (wid == 0) {
        int w = sh[lane];
        #pragma unroll
        for (int o = 1; o < 32; o <<= 1) {
            int y = __shfl_up_sync(0xffffffffu, w, o);
            if (lane >= o) w += y;
        }
        sh[lane] = w;
    }
    __syncthreads();
    int excl = x - sum + (wid > 0 ? sh[wid-1] : 0);
    int run = excl;
    if (base+0 < G) { g_blk[base+0] = run; run += v0; }
    if (base+1 < G) { g_blk[base+1] = run; run += v1; }
    if (base+2 < G) { g_blk[base+2] = run; run += v2; }
    if (base+3 < G) { g_blk[base+3] = run; run += v3; }
    if (t == 0) g_cnt[cidx] = sh[31];
}

__global__ void k_emit(long srcoff, long moff, int loff, int n) {
    int i = blockIdx.x*256 + threadIdx.x;
    bool a = (i < n) && (g_mem[srcoff + i] > 0.f);
    unsigned bal = __ballot_sync(0xffffffffu, a);
    __shared__ int ws[8];
    int lane = threadIdx.x & 31, wid = threadIdx.x >> 5;
    if (lane == 0) ws[wid] = __popc(bal);
    __syncthreads();
    int woff = 0;
    #pragma unroll
    for (int j = 0; j < 8; j++) if (j < wid) woff += ws[j];
    int pos = g_blk[blockIdx.x] + woff + __popc(bal & ((1u << lane) - 1u));
    if (a) g_list[loff + pos] = i;
    if (i < n) g_mem[moff + i] = a ? 1.f : 0.f;
}

// ------------------------------ mask kernels -------------------------------

__global__ void k_downmask(long inoff, long outoff, int S) {
    int n = Bn*S*S*S;
    int i = blockIdx.x*blockDim.x + threadIdx.x;
    if (i >= n) return;
    int S2 = S*S, S3 = S2*S;
    int b = i / S3; int r = i - b*S3;
    int z = r / S2; r -= z*S2;
    int y = r / S;  int x = r - y*S;
    int Si = 2*S, Si2 = Si*Si, Si3 = Si2*Si;
    const float* mi = g_mem + inoff + (long)b*Si3;
    float any = 0.f;
    #pragma unroll
    for (int a = 0; a < 2; a++)
    #pragma unroll
        for (int bb = 0; bb < 2; bb++)
    #pragma unroll
            for (int c = 0; c < 2; c++)
                any = fmaxf(any, mi[(2*z+a)*Si2 + (2*y+bb)*Si + (2*x+c)]);
    g_mem[outoff + i] = any > 0.f ? 1.f : 0.f;
}

__global__ void k_sparsify(long moff, long xoff, int n) {
    int i = blockIdx.x*blockDim.x + threadIdx.x;
    if (i >= n) return;
    float m = g_mem[moff + i];
    float r = 0.f;
    if (m > 0.f && g_mem[xoff + (long)i*16] > 0.f) r = 1.f;
    g_mem[moff + i] = r;
}

// ------------------------------- BatchNorm ---------------------------------

__global__ void k_bn_stats(long xoff, int loff, int cidx) {
    int cnt = g_cnt[cidx];
    float s[16], q[16];
    #pragma unroll
    for (int c = 0; c < 16; c++) { s[c] = 0.f; q[c] = 0.f; }
    for (int i = blockIdx.x*blockDim.x + threadIdx.x; i < cnt; i += gridDim.x*blockDim.x) {
        int site = g_list[loff + i];
        const float4* p = (const float4*)(g_mem + xoff + (long)site*16);
        #pragma unroll
        for (int h = 0; h < 4; h++) {
            float4 v = p[h];
            s[4*h+0] += v.x; q[4*h+0] += v.x*v.x;
            s[4*h+1] += v.y; q[4*h+1] += v.y*v.y;
            s[4*h+2] += v.z; q[4*h+2] += v.z*v.z;
            s[4*h+3] += v.w; q[4*h+3] += v.w*v.w;
        }
    }
    int lane = threadIdx.x & 31, wid = threadIdx.x >> 5;
    __shared__ float shs[8][16], shq[8][16];
    #pragma unroll
    for (int c = 0; c < 16; c++) {
        float a = s[c], b = q[c];
        #pragma unroll
        for (int o = 16; o > 0; o >>= 1) {
            a += __shfl_down_sync(0xffffffffu, a, o);
            b += __shfl_down_sync(0xffffffffu, b, o);
        }
        if (lane == 0) { shs[wid][c] = a; shq[wid][c] = b; }
    }
    __syncthreads();
    if (threadIdx.x < 16) {
        double A = 0.0, Bq = 0.0;
        #pragma unroll
        for (int j = 0; j < 8; j++) { A += (double)shs[j][threadIdx.x]; Bq += (double)shq[j][threadIdx.x]; }
        g_psum[threadIdx.x*GBN + blockIdx.x] = A;
        g_psq [threadIdx.x*GBN + blockIdx.x] = Bq;
    }
}

__global__ void k_bn_fin(const float* __restrict__ gamma, const float* __restrict__ beta, int cidx) {
    int c = threadIdx.x;
    if (c < Cn) {
        double s = 0.0, q = 0.0;
        for (int g = 0; g < GBN; g++) { s += g_psum[c*GBN + g]; q += g_psq[c*GBN + g]; }
        double n = (double)g_cnt[cidx]; if (n < 1.0) n = 1.0;
        double mean = s / n;
        double var  = q / n - mean*mean;
        double inv  = 1.0 / sqrt(var + 1e-4);
        double A    = (double)gamma[c] * inv;
        g_A[c]  = (float)A;
        g_Bb[c] = (float)((double)beta[c] - mean*A);
    }
}

__global__ void k_bn_apply(long xoff, int loff, int cidx) {
    int cnt = g_cnt[cidx];
    int i = blockIdx.x*blockDim.x + threadIdx.x;
    if (i >= cnt) return;
    int site = g_list[loff + i];
    float4* p = (float4*)(g_mem + xoff + (long)site*16);
    #pragma unroll
    for (int h = 0; h < 4; h++) {
        float4 v = p[h];
        v.x = fmaf(v.x, g_A[4*h+0], g_Bb[4*h+0]); v.x = v.x > 0.f ? v.x : 0.f;
        v.y = fmaf(v.y, g_A[4*h+1], g_Bb[4*h+1]); v.y = v.y > 0.f ? v.y : 0.f;
        v.z = fmaf(v.z, g_A[4*h+2], g_Bb[4*h+2]); v.z = v.z > 0.f ? v.z : 0.f;
        v.w = fmaf(v.w, g_A[4*h+3], g_Bb[4*h+3]); v.w = v.w > 0.f ? v.w : 0.f;
        p[h] = v;
    }
}

// ------------------------------ convolutions -------------------------------

__global__ void k_prep(long inoff, long outoff, const float* __restrict__ w,
                       int loff, int cidx) {
    int cnt = g_cnt[cidx];
    if (blockIdx.x * blockDim.x >= cnt) return;
    __shared__ __align__(16) ull sw[27*8];
    {
        const float2* ws = (const float2*)w;
        float2* wd = (float2*)sw;
        for (int i = threadIdx.x; i < 27*8; i += blockDim.x) wd[i] = ws[i];
    }
    __syncthreads();
    int i = blockIdx.x*blockDim.x + threadIdx.x;
    if (i >= cnt) return;
    int site = g_list[loff + i];
    const int lg = 6, S = 64;
    int b = site >> (3*lg), r = site & ((1<<(3*lg))-1);
    int z = r >> (2*lg), y = (r >> lg) & (S-1), x = r & (S-1);
    const float* in = g_mem + inoff;
    ull a[8];
    #pragma unroll
    for (int p = 0; p < 8; p++) a[p] = 0ull;
    #pragma unroll 1
    for (int dz = 0; dz < 3; dz++) {
        int zz = z + dz - 1; if ((unsigned)zz >= (unsigned)S) continue;
        #pragma unroll 1
        for (int dy = 0; dy < 3; dy++) {
            int yy = y + dy - 1; if ((unsigned)yy >= (unsigned)S) continue;
            #pragma unroll
            for (int dx = 0; dx < 3; dx++) {
                int xx = x + dx - 1; if ((unsigned)xx >= (unsigned)S) continue;
                float v = in[(b << (3*lg)) + (zz << (2*lg)) + (yy << lg) + xx];
                if (v == 0.f) continue;
                ull vv = pack2(v);
                const ulonglong2* wp = (const ulonglong2*)(sw + ((dz*3+dy)*3+dx)*8);
                #pragma unroll
                for (int h = 0; h < 4; h++) {
                    ulonglong2 wv = wp[h];
                    fma2(a[2*h+0], vv, wv.x);
                    fma2(a[2*h+1], vv, wv.y);
                }
            }
        }
    }
    STORE16(g_mem + outoff + (long)site*16, a);
}

__global__ void __launch_bounds__(128) k_conv3c(long inoff, long outoff,
        const float* __restrict__ w, long moff, int loff, int cidx, int lg) {
    int cnt = g_cnt[cidx];
    if (blockIdx.x * 256 >= cnt) return;
    __shared__ __align__(16) ull sw[27*128];
    {
        const float2* ws = (const float2*)w;
        float2* wd = (float2*)sw;
        for (int i = threadIdx.x; i < 27*128; i += blockDim.x) wd[i] = ws[i];
    }
    __syncthreads();
    int t = blockIdx.x*128 + threadIdx.x;
    int i0 = 2*t, i1 = i0 + 1;
    if (i0 >= cnt) return;
    bool has1 = i1 < cnt;
    int S = 1 << lg;
    int site0 = g_list[loff + i0];
    int site1 = has1 ? g_list[loff + i1] : site0;
    int b0 = site0 >> (3*lg), r0 = site0 & ((1<<(3*lg))-1);
    int z0 = r0 >> (2*lg), y0 = (r0 >> lg) & (S-1), x0 = r0 & (S-1);
    int b1 = site1 >> (3*lg), r1 = site1 & ((1<<(3*lg))-1);
    int z1 = r1 >> (2*lg), y1 = (r1 >> lg) & (S-1), x1 = r1 & (S-1);
    const float* __restrict__ in = g_mem + inoff;
    const float* __restrict__ mm = g_mem + moff;
    ull a0[8], a1[8];
    #pragma unroll
    for (int p = 0; p < 8; p++) { a0[p] = 0ull; a1[p] = 0ull; }
    #pragma unroll 1
    for (int dz = 0; dz < 3; dz++) {
        #pragma unroll 1
        for (int dy = 0; dy < 3; dy++) {
            #pragma unroll 1
            for (int dx = 0; dx < 3; dx++) {
                int zz0 = z0+dz-1, yy0 = y0+dy-1, xx0 = x0+dx-1;
                int zz1 = z1+dz-1, yy1 = y1+dy-1, xx1 = x1+dx-1;
                bool ok0 = ((unsigned)zz0 < (unsigned)S) & ((unsigned)yy0 < (unsigned)S) & ((unsigned)xx0 < (unsigned)S);
                bool ok1 = has1 & ((unsigned)zz1 < (unsigned)S) & ((unsigned)yy1 < (unsigned)S) & ((unsigned)xx1 < (unsigned)S);
                int nb0 = 0, nb1 = 0;
                if (ok0) { nb0 = (b0 << (3*lg)) + (zz0 << (2*lg)) + (yy0 << lg) + xx0; ok0 = mm[nb0] != 0.f; }
                if (ok1) { nb1 = (b1 << (3*lg)) + (zz1 << (2*lg)) + (yy1 << lg) + xx1; ok1 = mm[nb1] != 0.f; }
                if (!(ok0 | ok1)) continue;
                float q0f[16], q1f[16];
                #pragma unroll
                for (int c = 0; c < 16; c++) { q0f[c] = 0.f; q1f[c] = 0.f; }
                if (ok0) LOAD16(q0f, in + (long)nb0*16);
                if (ok1) LOAD16(q1f, in + (long)nb1*16);
                const ull* wr = sw + ((dz*3+dy)*3+dx)*128;
                #pragma unroll
                for (int c = 0; c < 16; c++) {
                    ull v0 = pack2(q0f[c]);
                    ull v1 = pack2(q1f[c]);
                    const ulonglong2* wp = (const ulonglong2*)(wr + c*8);
                    #pragma unroll
                    for (int h = 0; h < 4; h++) {
                        ulonglong2 wv = wp[h];
                        fma2(a0[2*h+0], v0, wv.x); fma2(a0[2*h+1], v0, wv.y);
                        fma2(a1[2*h+0], v1, wv.x); fma2(a1[2*h+1], v1, wv.y);
                    }
                }
            }
        }
    }
    STORE16(g_mem + outoff + (long)site0*16, a0);
    if (has1) STORE16(g_mem + outoff + (long)site1*16, a1);
}

__global__ void __launch_bounds__(128) k_conv4c(long inoff, long outoff,
        const float* __restrict__ w, long moff, int loff, int cidx, int lg) {
    int cnt = g_cnt[cidx];
    if (blockIdx.x * 256 >= cnt) return;
    __shared__ __align__(16) ull sw[2048];
    int t = blockIdx.x*128 + threadIdx.x;
    int i0 = 2*t, i1 = i0 + 1;
    bool act0 = i0 < cnt, act1 = i1 < cnt;
    int S = 1 << lg;
    int site0 = act0 ? g_list[loff + i0] : 0;
    int site1 = act1 ? g_list[loff + i1] : 0;
    int b0 = site0 >> (3*lg), r0 = site0 & ((1<<(3*lg))-1);
    int z0 = r0 >> (2*lg), y0 = (r0 >> lg) & (S-1), x0 = r0 & (S-1);
    int b1 = site1 >> (3*lg), r1 = site1 & ((1<<(3*lg))-1);
    int z1 = r1 >> (2*lg), y1 = (r1 >> lg) & (S-1), x1 = r1 & (S-1);
    const float* __restrict__ in = g_mem + inoff;
    const float* __restrict__ mm = g_mem + moff;
    ull a0[8], a1[8];
    #pragma unroll
    for (int p = 0; p < 8; p++) { a0[p] = 0ull; a1[p] = 0ull; }
    #pragma unroll 1
    for (int dz = 0; dz < 4; dz++) {
        __syncthreads();
        {
            const float2* ws = (const float2*)(w + dz*4096);
            float2* wd = (float2*)sw;
            for (int i = threadIdx.x; i < 2048; i += 128) wd[i] = ws[i];
        }
        __syncthreads();
        int zz0 = z0 + dz - 1, zz1 = z1 + dz - 1;
        bool zok0 = act0 & ((unsigned)zz0 < (unsigned)S);
        bool zok1 = act1 & ((unsigned)zz1 < (unsigned)S);
        if (!(zok0 | zok1)) continue;
        #pragma unroll 1
        for (int dy = 0; dy < 4; dy++) {
            int yy0 = y0+dy-1, yy1 = y1+dy-1;
            bool yok0 = zok0 & ((unsigned)yy0 < (unsigned)S);
            bool yok1 = zok1 & ((unsigned)yy1 < (unsigned)S);
            if (!(yok0 | yok1)) continue;
            #pragma unroll 1
            for (int dx = 0; dx < 4; dx++) {
                int xx0 = x0+dx-1, xx1 = x1+dx-1;
                bool ok0 = yok0 & ((unsigned)xx0 < (unsigned)S);
                bool ok1 = yok1 & ((unsigned)xx1 < (unsigned)S);
                int nb0 = 0, nb1 = 0;
                if (ok0) { nb0 = (b0 << (3*lg)) + (zz0 << (2*lg)) + (yy0 << lg) + xx0; ok0 = mm[nb0] != 0.f; }
                if (ok1) { nb1 = (b1 << (3*lg)) + (zz1 << (2*lg)) + (yy1 << lg) + xx1; ok1 = mm[nb1] != 0.f; }
                if (!(ok0 | ok1)) continue;
                float q0f[16], q1f[16];
                #pragma unroll
                for (int c = 0; c < 16; c++) { q0f[c] = 0.f; q1f[c] = 0.f; }
                if (ok0) LOAD16(q0f, in + (long)nb0*16);
                if (ok1) LOAD16(q1f, in + (long)nb1*16);
                const ull* wr = sw + (dy*4+dx)*128;
                #pragma unroll
                for (int c = 0; c < 16; c++) {
                    ull v0 = pack2(q0f[c]);
                    ull v1 = pack2(q1f[c]);
                    const ulonglong2* wp = (const ulonglong2*)(wr + c*8);
                    #pragma unroll
                    for (int h = 0; h < 4; h++) {
                        ulonglong2 wv = wp[h];
                        fma2(a0[2*h+0], v0, wv.x); fma2(a0[2*h+1], v0, wv.y);
                        fma2(a1[2*h+0], v1, wv.x); fma2(a1[2*h+1], v1, wv.y);
                    }
                }
            }
        }
    }
    if (act0) STORE16(g_mem + outoff + (long)site0*16, a0);
    if (act1) STORE16(g_mem + outoff + (long)site1*16, a1);
}

__global__ void __launch_bounds__(128) k_downc(long inoff, long outoff,
        const float* __restrict__ w, long mfoff, int loff, int cidx, int lg) {
    int cnt = g_cnt[cidx];
    if (blockIdx.x * 256 >= cnt) return;
    __shared__ __align__(16) ull sw[8*128];
    {
        const float2* ws = (const float2*)w;
        float2* wd = (float2*)sw;
        for (int i = threadIdx.x; i < 8*128; i += blockDim.x) wd[i] = ws[i];
    }
    __syncthreads();
    int t = blockIdx.x*128 + threadIdx.x;
    int i0 = 2*t, i1 = i0 + 1;
    if (i0 >= cnt) return;
    bool has1 = i1 < cnt;
    int S = 1 << lg, lgf = lg + 1;
    int site0 = g_list[loff + i0];
    int site1 = has1 ? g_list[loff + i1] : site0;
    int b0 = site0 >> (3*lg), r0 = site0 & ((1<<(3*lg))-1);
    int z0 = r0 >> (2*lg), y0 = (r0 >> lg) & (S-1), x0 = r0 & (S-1);
    int b1 = site1 >> (3*lg), r1 = site1 & ((1<<(3*lg))-1);
    int z1 = r1 >> (2*lg), y1 = (r1 >> lg) & (S-1), x1 = r1 & (S-1);
    const float* __restrict__ in = g_mem + inoff;
    const float* __restrict__ mf = g_mem + mfoff;
    ull a0[8], a1[8];
    #pragma unroll
    for (int p = 0; p < 8; p++) { a0[p] = 0ull; a1[p] = 0ull; }
    #pragma unroll 1
    for (int ta = 0; ta < 2; ta++)
    #pragma unroll 1
    for (int tb = 0; tb < 2; tb++)
    #pragma unroll 1
    for (int tc = 0; tc < 2; tc++) {
        int nb0 = (b0 << (3*lgf)) + ((2*z0+ta) << (2*lgf)) + ((2*y0+tb) << lgf) + (2*x0+tc);
        int nb1 = (b1 << (3*lgf)) + ((2*z1+ta) << (2*lgf)) + ((2*y1+tb) << lgf) + (2*x1+tc);
        bool ok0 = mf[nb0] != 0.f;
        bool ok1 = has1 && (mf[nb1] != 0.f);
        if (!(ok0 | ok1)) continue;
        float q0f[16], q1f[16];
        #pragma unroll
        for (int c = 0; c < 16; c++) { q0f[c] = 0.f; q1f[c] = 0.f; }
        if (ok0) LOAD16(q0f, in + (long)nb0*16);
        if (ok1) LOAD16(q1f, in + (long)nb1*16);
        const ull* wr = sw + ((ta*2+tb)*2+tc)*128;
        #pragma unroll
        for (int c = 0; c < 16; c++) {
            ull v0 = pack2(q0f[c]);
            ull v1 = pack2(q1f[c]);
            const ulonglong2* wp = (const ulonglong2*)(wr + c*8);
            #pragma unroll
            for (int h = 0; h < 4; h++) {
                ulonglong2 wv = wp[h];
                fma2(a0[2*h+0], v0, wv.x); fma2(a0[2*h+1], v0, wv.y);
                fma2(a1[2*h+0], v1, wv.x); fma2(a1[2*h+1], v1, wv.y);
            }
        }
    }
    STORE16(g_mem + outoff + (long)site0*16, a0);
    if (has1) STORE16(g_mem + outoff + (long)site1*16, a1);
}

__global__ void k_upc(long inoff, long outoff, const float* __restrict__ w,
                      long mcoff, int loff, int cidx, int lg) {
    int cnt = g_cnt[cidx];
    if (blockIdx.x * blockDim.x >= cnt) return;
    __shared__ __align__(16) ull sw[8*128];
    {
        const float2* ws = (const float2*)w;
        float2* wd = (float2*)sw;
        for (int i = threadIdx.x; i < 8*128; i += blockDim.x) wd[i] = ws[i];
    }
    __syncthreads();
    int i = blockIdx.x*blockDim.x + threadIdx.x;
    if (i >= cnt) return;
    int S = 1 << lg, lgc = lg - 1;
    int site = g_list[loff + i];
    int b = site >> (3*lg), r = site & ((1<<(3*lg))-1);
    int z = r >> (2*lg), y = (r >> lg) & (S-1), x = r & (S-1);
    int pn = (b << (3*lgc)) + ((z>>1) << (2*lgc)) + ((y>>1) << lgc) + (x>>1);
    ull a[8];
    #pragma unroll
    for (int p = 0; p < 8; p++) a[p] = 0ull;
    if (g_mem[mcoff + pn] != 0.f) {
        float qf[16];
        LOAD16(qf, g_mem + inoff + (long)pn*16);
        int tap = ((1-(z&1))*2 + (1-(y&1)))*2 + (1-(x&1));
        const ull* wr = sw + tap*128;
        #pragma unroll
        for (int c = 0; c < 16; c++) {
            ull v = pack2(qf[c]);
            const ulonglong2* wp = (const ulonglong2*)(wr + c*8);
            #pragma unroll
            for (int h = 0; h < 4; h++) {
                ulonglong2 wv = wp[h];
                fma2(a[2*h+0], v, wv.x);
                fma2(a[2*h+1], v, wv.y);
            }
        }
    }
    STORE16(g_mem + outoff + (long)site*16, a);
}

__global__ void k_convout(long inoff, float* __restrict__ outp,
                          const float* __restrict__ w, long moff, int loff, int cidx) {
    int cnt = g_cnt[cidx];
    if (blockIdx.x * blockDim.x >= cnt) return;
    __shared__ float sw[27*16];
    for (int i = threadIdx.x; i < 27*16; i += blockDim.x) sw[i] = w[i];
    __syncthreads();
    int i = blockIdx.x*blockDim.x + threadIdx.x;
    if (i >= cnt) return;
    const int lg = 6, S = 64;
    int site = g_list[loff + i];
    int b = site >> (3*lg), r = site & ((1<<(3*lg))-1);
    int z = r >> (2*lg), y = (r >> lg) & (S-1), x = r & (S-1);
    const float* __restrict__ in = g_mem + inoff;
    const float* __restrict__ mm = g_mem + moff;
    float acc = 0.f;
    #pragma unroll 1
    for (int dz = 0; dz < 3; dz++) {
        int zz = z + dz - 1; if ((unsigned)zz >= (unsigned)S) continue;
        #pragma unroll 1
        for (int dy = 0; dy < 3; dy++) {
            int yy = y + dy - 1; if ((unsigned)yy >= (unsigned)S) continue;
            #pragma unroll
            for (int dx = 0; dx < 3; dx++) {
                int xx = x + dx - 1; if ((unsigned)xx >= (unsigned)S) continue;
                int nb = (b << (3*lg)) + (zz << (2*lg)) + (yy << lg) + xx;
                if (mm[nb] == 0.f) continue;
                float qf[16];
                LOAD16(qf, in + (long)nb*16);
                const float* wr = sw + ((dz*3+dy)*3+dx)*16;
                #pragma unroll
                for (int c = 0; c < 16; c++) acc = fmaf(qf[c], wr[c], acc);
            }
        }
    }
    outp[site] = acc;
}

__global__ void k_hidden(float* __restrict__ outp, long xoff, long moff) {
    int i = blockIdx.x*blockDim.x + threadIdx.x;
    if (i >= NS3) return;
    float mv = g_mem[moff + i];
    int b = i >> 9, sp = i & 511;
    const float* xp = g_mem + xoff + (long)i*16;
    #pragma unroll
    for (int c = 0; c < 16; c++)
        outp[b*8192 + c*512 + sp] = (mv > 0.f) ? xp[c] : 0.f;
}

// ------------------------------- host --------------------------------------

static void build_list(long srcoff, long moff, int loff, int cidx, int n) {
    int G = n / 256;
    k_count<<<G, 256>>>(srcoff, n);
    k_scan<<<1, 1024>>>(G, cidx);
    k_emit<<<G, 256>>>(srcoff, moff, loff, n);
}

static void bn_stage(long xoff, int loff, int cidx, const float* gamma, const float* beta, int maxc) {
    k_bn_stats<<<GBN, 256>>>(xoff, loff, cidx);
    k_bn_fin<<<1, 32>>>(gamma, beta, cidx);
    k_bn_apply<<<CDIV(maxc, 256), 256>>>(xoff, loff, cidx);
}

extern "C" void kernel_launch(void* const* d_in, const int* in_sizes, int n_in,
                              void* d_out, int out_size) {
    const float* data      = (const float*)d_in[0];
    const int*   cid       = (const int*)  d_in[1];
    const float* w_prep    = (const float*)d_in[2];
    const float* enc_gamma = (const float*)d_in[3];
    const float* enc_beta  = (const float*)d_in[4];
    const float* enc_wsub  = (const float*)d_in[5];
    const float* enc_wdown = (const float*)d_in[6];
    const float* dec_gamma = (const float*)d_in[7];
    const float* dec_beta  = (const float*)d_in[8];
    const float* dec_wup   = (const float*)d_in[9];
    const float* dec_wsub3 = (const float*)d_in[10];
    const float* dec_wsub4 = (const float*)d_in[11];
    const float* w_out     = (const float*)d_in[12];
    float* outp = (float*)d_out;
    int npts = in_sizes[0] / 5;
    int maxc0 = npts < NS0 ? npts : NS0;
    const int T = 256;
    (void)n_in; (void)out_size;

    // input scatter + level-0 list
    k_zero4<<<CDIV(NS0/4, T), T>>>(OFF_XA, NS0/4);
    k_scatter<<<CDIV(npts, T), T>>>(data, cid, npts);
    build_list(OFF_XA, OFF_M0, LOFF0, 0, NS0);

    // prepare conv (counts -> 16ch)
    k_prep<<<CDIV(maxc0, T), T>>>(OFF_XA, OFF_XB, w_prep, LOFF0, 0);

    // encoder stage 0 (64^3 -> 32^3)
    bn_stage(OFF_XB, LOFF0, 0, enc_gamma + 0, enc_beta + 0, maxc0);
    k_conv3c<<<CDIV(maxc0, 256), 128>>>(OFF_XB, OFF_XA, enc_wsub + 0, OFF_M0, LOFF0, 0, 6);
    k_downmask<<<CDIV(NS1, T), T>>>(OFF_M0, OFF_M1, 32);
    build_list(OFF_M1, OFF_M1, LOFF1, 1, NS1);
    k_downc<<<CDIV(NS1, 256), 128>>>(OFF_XA, OFF_XB, enc_wdown + 0, OFF_M0, LOFF1, 1, 5);

    // encoder stage 1 (32^3 -> 16^3)
    bn_stage(OFF_XB, LOFF1, 1, enc_gamma + 16, enc_beta + 16, NS1);
    k_conv3c<<<CDIV(NS1, 256), 128>>>(OFF_XB, OFF_XA, enc_wsub + 6912, OFF_M1, LOFF1, 1, 5);
    k_downmask<<<CDIV(NS2, T), T>>>(OFF_M1, OFF_M2, 16);
    build_list(OFF_M2, OFF_M2, LOFF2, 2, NS2);
    k_downc<<<CDIV(NS2, 256), 128>>>(OFF_XA, OFF_XB, enc_wdown + 2048, OFF_M1, LOFF2, 2, 4);

    // encoder stage 2 (16^3 -> 8^3)
    bn_stage(OFF_XB, LOFF2, 2, enc_gamma + 32, enc_beta + 32, NS2);
    k_conv3c<<<CDIV(NS2, 256), 128>>>(OFF_XB, OFF_XA, enc_wsub + 13824, OFF_M2, LOFF2, 2, 4);
    k_downmask<<<CDIV(NS3, T), T>>>(OFF_M2, OFF_M3, 8);
    build_list(OFF_M3, OFF_M3, LOFF3, 3, NS3);
    k_downc<<<CDIV(NS3, 256), 128>>>(OFF_XA, OFF_XB, enc_wdown + 4096, OFF_M2, LOFF3, 3, 3);

    // hidden output
    k_hidden<<<CDIV(NS3, T), T>>>(outp, OFF_XB, OFF_M3);

    // decoder j=0 (8^3 -> 16^3)
    bn_stage(OFF_XB, LOFF3, 3, dec_gamma + 0, dec_beta + 0, NS3);
    k_upc<<<CDIV(NS2, T), T>>>(OFF_XB, OFF_XA, dec_wup + 0, OFF_M3, LOFF2, 2, 4);
    k_conv3c<<<CDIV(NS2, 256), 128>>>(OFF_XA, OFF_XB, dec_wsub3 + 0, OFF_M2, LOFF2, 2, 4);
    k_sparsify<<<CDIV(NS2, T), T>>>(OFF_M2, OFF_XB, NS2);
    build_list(OFF_M2, OFF_M2, LOFF2, 2, NS2);
    k_conv4c<<<CDIV(NS2, 256), 128>>>(OFF_XB, OFF_XA, dec_wsub4 + 0, OFF_M2, LOFF2, 2, 4);

    // decoder j=1 (16^3 -> 32^3)
    bn_stage(OFF_XA, LOFF2, 2, dec_gamma + 16, dec_beta + 16, NS2);
    k_upc<<<CDIV(NS1, T), T>>>(OFF_XA, OFF_XB, dec_wup + 2048, OFF_M2, LOFF1, 1, 5);
    k_conv3c<<<CDIV(NS1, 256), 128>>>(OFF_XB, OFF_XA, dec_wsub3 + 6912, OFF_M1, LOFF1, 1, 5);
    k_sparsify<<<CDIV(NS1, T), T>>>(OFF_M1, OFF_XA, NS1);
    build_list(OFF_M1, OFF_M1, LOFF1, 1, NS1);
    k_conv4c<<<CDIV(NS1, 256), 128>>>(OFF_XA, OFF_XB, dec_wsub4 + 16384, OFF_M1, LOFF1, 1, 5);

    // decoder j=2 (32^3 -> 64^3)
    bn_stage(OFF_XB, LOFF1, 1, dec_gamma + 32, dec_beta + 32, NS1);
    k_upc<<<CDIV(maxc0, T), T>>>(OFF_XB, OFF_XA, dec_wup + 4096, OFF_M1, LOFF0, 0, 6);
    k_conv3c<<<CDIV(maxc0, 256), 128>>>(OFF_XA, OFF_XB, dec_wsub3 + 13824, OFF_M0, LOFF0, 0, 6);
    k_sparsify<<<CDIV(NS0, T), T>>>(OFF_M0, OFF_XB, NS0);
    build_list(OFF_M0, OFF_M0, LOFF0, 0, NS0);
    k_conv4c<<<CDIV(maxc0, 256), 128>>>(OFF_XB, OFF_XA, dec_wsub4 + 32768, OFF_M0, LOFF0, 0, 6);

    // output conv (16->1, k3) -> out region (zero inactive sites first)
    k_zerop4<<<CDIV(NS0/4, T), T>>>(outp + Cn*NS3, NS0/4);
    k_convout<<<CDIV(maxc0, T), T>>>(OFF_XA, outp + Cn*NS3, w_out, OFF_M0, LOFF0, 0);
}

// round 5
// speedup vs baseline: 1.9079x; 1.1617x over previous
#include <cuda_runtime.h>
#include <math.h>

#define CDIV(a,b) (((a)+(b)-1)/(b))
#define NS0 (4*64*64*64)
#define NS1 (4*32*32*32)
#define NS2 (4*16*16*16)
#define NS3 (4*8*8*8)
#define GBN 128

// feature buffers: 2 x (4 planes x NS0 float4)  (compacted by rank)
__device__ __align__(16) float g_mem[2*16*NS0];
#define BUF_A 0L
#define BUF_B ((long)4*NS0)

// int arena: idx maps (site->rank or -1) and rank->site lists
#define IA0 0
#define IA1 (IA0+NS0)
#define IA2 (IA1+NS1)
#define IA3 (IA2+NS2)
#define IB0 (IA3+NS3)
#define IB1 (IB0+NS0)
#define IB2 (IB1+NS1)
#define LA0 (IB2+NS2)
#define LA1 (LA0+NS0)
#define LA2 (LA1+NS1)
#define LA3 (LA2+NS2)
#define LB0 (LA3+NS3)
#define LB1 (LB0+NS0)
#define LB2 (LB1+NS1)
#define ITOT (LB2+NS2)
__device__ int g_int[ITOT];

// counts: 0=A0 1=A1 2=A2 3=A3 4=B2 5=B1 6=B0
#define CA0 0
#define CA1 1
#define CA2 2
#define CA3 3
#define CB2 4
#define CB1 5
#define CB0 6
__device__ int    g_cnt[8];
__device__ int    g_blk[4096];
__device__ double g_psum[16*GBN];
__device__ double g_psq [16*GBN];
__device__ float  g_A[16];
__device__ float  g_Bb[16];
__device__ int    g_ticket;

typedef unsigned long long ull;

__device__ __forceinline__ ull pack2(float v) {
    ull r; asm("mov.b64 %0, {%1, %1};" : "=l"(r) : "f"(v)); return r;
}
__device__ __forceinline__ void fma2(ull& a, ull v, ull w) {
    asm("fma.rn.f32x2 %0, %1, %2, %0;" : "+l"(a) : "l"(v), "l"(w));
}
__device__ __forceinline__ float2 unpack2(ull a) {
    float2 f; asm("mov.b64 {%0, %1}, %2;" : "=f"(f.x), "=f"(f.y) : "l"(a)); return f;
}

#define LOADP(dst, f4, r) do { float4 _v; \
    _v=(f4)[(r)];          dst[0]=_v.x; dst[1]=_v.y; dst[2]=_v.z; dst[3]=_v.w; \
    _v=(f4)[NS0+(r)];      dst[4]=_v.x; dst[5]=_v.y; dst[6]=_v.z; dst[7]=_v.w; \
    _v=(f4)[2*NS0+(r)];    dst[8]=_v.x; dst[9]=_v.y; dst[10]=_v.z; dst[11]=_v.w; \
    _v=(f4)[3*NS0+(r)];    dst[12]=_v.x; dst[13]=_v.y; dst[14]=_v.z; dst[15]=_v.w; } while(0)

#define STOREP(f4, r, a) do { float2 _f; float4 _q; \
    _f=unpack2(a[0]); _q.x=_f.x; _q.y=_f.y; _f=unpack2(a[1]); _q.z=_f.x; _q.w=_f.y; (f4)[(r)]=_q; \
    _f=unpack2(a[2]); _q.x=_f.x; _q.y=_f.y; _f=unpack2(a[3]); _q.z=_f.x; _q.w=_f.y; (f4)[NS0+(r)]=_q; \
    _f=unpack2(a[4]); _q.x=_f.x; _q.y=_f.y; _f=unpack2(a[5]); _q.z=_f.x; _q.w=_f.y; (f4)[2*NS0+(r)]=_q; \
    _f=unpack2(a[6]); _q.x=_f.x; _q.y=_f.y; _f=unpack2(a[7]); _q.z=_f.x; _q.w=_f.y; (f4)[3*NS0+(r)]=_q; } while(0)

// --------------------------- input -----------------------------------------

__global__ void k_zero4(long off, int n4) {
    float4* p = (float4*)(g_mem + off);
    float4 z = make_float4(0.f,0.f,0.f,0.f);
    for (int i = blockIdx.x*blockDim.x + threadIdx.x; i < n4; i += gridDim.x*blockDim.x)
        p[i] = z;
}

__global__ void k_scatter(const float* __restrict__ data, const int* __restrict__ cid, int n) {
    int i = blockIdx.x*blockDim.x + threadIdx.x;
    if (i >= n) return;
    int z = (int)data[i*5+0];
    int y = (int)data[i*5+1];
    int x = (int)data[i*5+2];
    int b = cid[i];
    atomicAdd(&g_mem[((((long)b*64 + z)*64 + y)*64 + x)], 1.0f);
}

// --------------------- compaction (count + emit w/ self-scan) --------------

__device__ __forceinline__ bool is_active(int mode, int i, int lg, long foff, int ioff) {
    if (mode == 0) return g_mem[foff + i] > 0.f;
    if (mode == 1) {
        int S = 1 << lg;
        int b = i >> (3*lg), r = i & ((1<<(3*lg))-1);
        int z = r >> (2*lg), y = (r >> lg) & (S-1), x = r & (S-1);
        int flg = lg + 1;
        #pragma unroll
        for (int a = 0; a < 2; a++)
        #pragma unroll
        for (int bb = 0; bb < 2; bb++)
        #pragma unroll
        for (int c = 0; c < 2; c++) {
            int nb = (b << (3*flg)) + ((2*z+a) << (2*flg)) + ((2*y+bb) << flg) + (2*x+c);
            if (g_int[ioff + nb] >= 0) return true;
        }
        return false;
    }
    int r = g_int[ioff + i];
    if (r < 0) return false;
    return ((const float4*)g_mem + foff)[r].x > 0.f;
}

__global__ void k_count(int mode, int lg, long foff, int ioff) {
    int i = blockIdx.x*256 + threadIdx.x;
    bool a = is_active(mode, i, lg, foff, ioff);
    unsigned bal = __ballot_sync(0xffffffffu, a);
    __shared__ int ws[8];
    if ((threadIdx.x & 31) == 0) ws[threadIdx.x >> 5] = __popc(bal);
    __syncthreads();
    if (threadIdx.x == 0) {
        int s = 0;
        #pragma unroll
        for (int j = 0; j < 8; j++) s += ws[j];
        g_blk[blockIdx.x] = s;
    }
}

__global__ void k_emit(int mode, int lg, long foff, int ioff,
                       int idxout, int listout, int cidx) {
    int t = threadIdx.x;
    int i = blockIdx.x*256 + t;
    bool a = is_active(mode, i, lg, foff, ioff);
    unsigned bal = __ballot_sync(0xffffffffu, a);
    __shared__ int sh[48];
    int lane = t & 31, wid = t >> 5;
    int pre = 0;
    for (int j = t; j < blockIdx.x; j += 256) pre += g_blk[j];
    #pragma unroll
    for (int o = 16; o > 0; o >>= 1) pre += __shfl_down_sync(0xffffffffu, pre, o);
    if (lane == 0) sh[wid] = pre;
    if (lane == 0) sh[40 + wid] = __popc(bal);
    __syncthreads();
    if (t == 0) {
        int s = 0;
        #pragma unroll
        for (int j = 0; j < 8; j++) s += sh[j];
        sh[32] = s;
    }
    __syncthreads();
    int base = sh[32];
    int woff = 0;
    #pragma unroll
    for (int j = 0; j < 8; j++) if (j < wid) woff += sh[40 + j];
    int pos = base + woff + __popc(bal & ((1u << lane) - 1u));
    g_int[idxout + i] = a ? pos : -1;
    if (a) g_int[listout + pos] = i;
    if (blockIdx.x == gridDim.x - 1 && t == 0) {
        int bc = 0;
        #pragma unroll
        for (int j = 0; j < 8; j++) bc += sh[40 + j];
        g_cnt[cidx] = base + bc;
    }
}

// ------------------------------- BatchNorm ---------------------------------

__global__ void k_bnstats(long in4, int cidx, const float* __restrict__ gamma,
                          const float* __restrict__ beta) {
    int cnt = g_cnt[cidx];
    const float4* f = (const float4*)g_mem + in4;
    float s[16], q[16];
    #pragma unroll
    for (int c = 0; c < 16; c++) { s[c] = 0.f; q[c] = 0.f; }
    for (int i = blockIdx.x*256 + threadIdx.x; i < cnt; i += GBN*256) {
        #pragma unroll
        for (int h = 0; h < 4; h++) {
            float4 v = f[h*NS0 + i];
            s[4*h+0] += v.x; q[4*h+0] += v.x*v.x;
            s[4*h+1] += v.y; q[4*h+1] += v.y*v.y;
            s[4*h+2] += v.z; q[4*h+2] += v.z*v.z;
            s[4*h+3] += v.w; q[4*h+3] += v.w*v.w;
        }
    }
    int lane = threadIdx.x & 31, wid = threadIdx.x >> 5;
    __shared__ float shs[8][16], shq[8][16];
    #pragma unroll
    for (int c = 0; c < 16; c++) {
        float a = s[c], b = q[c];
        #pragma unroll
        for (int o = 16; o > 0; o >>= 1) {
            a += __shfl_down_sync(0xffffffffu, a, o);
            b += __shfl_down_sync(0xffffffffu, b, o);
        }
        if (lane == 0) { shs[wid][c] = a; shq[wid][c] = b; }
    }
    __syncthreads();
    if (threadIdx.x < 16) {
        double A = 0.0, Bq = 0.0;
        #pragma unroll
        for (int j = 0; j < 8; j++) { A += (double)shs[j][threadIdx.x]; Bq += (double)shq[j][threadIdx.x]; }
        g_psum[threadIdx.x*GBN + blockIdx.x] = A;
        g_psq [threadIdx.x*GBN + blockIdx.x] = Bq;
    }
    __threadfence();
    __shared__ int lastf;
    if (threadIdx.x == 0) {
        int o = atomicAdd(&g_ticket, 1);
        lastf = (o == GBN - 1) ? 1 : 0;
    }
    __syncthreads();
    if (lastf) {
        __threadfence();
        if (threadIdx.x < 16) {
            int c = threadIdx.x;
            volatile double* vs = g_psum;
            volatile double* vq = g_psq;
            double S = 0.0, Q = 0.0;
            for (int g = 0; g < GBN; g++) { S += vs[c*GBN + g]; Q += vq[c*GBN + g]; }
            double n = (double)cnt; if (n < 1.0) n = 1.0;
            double mean = S / n;
            double var  = Q / n - mean*mean;
            double inv  = 1.0 / sqrt(var + 1e-4);
            double Af   = (double)gamma[c] * inv;
            g_A[c]  = (float)Af;
            g_Bb[c] = (float)((double)beta[c] - mean*Af);
        }
        if (threadIdx.x == 0) g_ticket = 0;
    }
}

__global__ void k_bnapply(long in4, int cidx) {
    int cnt = g_cnt[cidx];
    int i = blockIdx.x*256 + threadIdx.x;
    if (i >= cnt) return;
    float4* f = (float4*)g_mem + in4;
    #pragma unroll
    for (int h = 0; h < 4; h++) {
        float4 v = f[h*NS0 + i];
        v.x = fmaf(v.x, g_A[4*h+0], g_Bb[4*h+0]); v.x = v.x > 0.f ? v.x : 0.f;
        v.y = fmaf(v.y, g_A[4*h+1], g_Bb[4*h+1]); v.y = v.y > 0.f ? v.y : 0.f;
        v.z = fmaf(v.z, g_A[4*h+2], g_Bb[4*h+2]); v.z = v.z > 0.f ? v.z : 0.f;
        v.w = fmaf(v.w, g_A[4*h+3], g_Bb[4*h+3]); v.w = v.w > 0.f ? v.w : 0.f;
        f[h*NS0 + i] = v;
    }
}

// ------------------------------ convolutions -------------------------------

__global__ void k_prep(long out4, const float* __restrict__ w) {
    int cnt = g_cnt[CA0];
    if (blockIdx.x*256 >= cnt) return;
    __shared__ __align__(16) float sw[432];
    for (int i = threadIdx.x; i < 432; i += 256) sw[i] = w[i];
    __syncthreads();
    int i = blockIdx.x*256 + threadIdx.x;
    if (i >= cnt) return;
    int site = g_int[LA0 + i];
    const int lg = 6, S = 64;
    int b = site >> 18, r = site & 0x3ffff;
    int z = r >> 12, y = (r >> 6) & 63, x = r & 63;
    ull a[8];
    #pragma unroll
    for (int p = 0; p < 8; p++) a[p] = 0ull;
    #pragma unroll 1
    for (int dz = 0; dz < 3; dz++) {
        int zz = z + dz - 1; if ((unsigned)zz >= (unsigned)S) continue;
        #pragma unroll 1
        for (int dy = 0; dy < 3; dy++) {
            int yy = y + dy - 1; if ((unsigned)yy >= (unsigned)S) continue;
            #pragma unroll
            for (int dx = 0; dx < 3; dx++) {
                int xx = x + dx - 1; if ((unsigned)xx >= (unsigned)S) continue;
                float v = g_mem[(b << (3*lg)) + (zz << (2*lg)) + (yy << lg) + xx];
                if (v == 0.f) continue;
                ull vv = pack2(v);
                const ulonglong2* wp = (const ulonglong2*)(sw + ((dz*3+dy)*3+dx)*16);
                #pragma unroll
                for (int h = 0; h < 4; h++) {
                    ulonglong2 wv = wp[h];
                    fma2(a[2*h+0], vv, wv.x);
                    fma2(a[2*h+1], vv, wv.y);
                }
            }
        }
    }
    float4* fo = (float4*)g_mem + out4;
    STOREP(fo, i, a);
}

__global__ void __launch_bounds__(128) k_conv3(long in4, long out4,
        const float* __restrict__ w, int ioff, int loff, int cidx, int lg) {
    int cnt = g_cnt[cidx];
    if (blockIdx.x*256 >= cnt) return;
    __shared__ __align__(16) float sw[6912];
    {
        const float4* ws = (const float4*)w;
        float4* wd = (float4*)sw;
        for (int i = threadIdx.x; i < 1728; i += 128) wd[i] = ws[i];
    }
    __syncthreads();
    int t = blockIdx.x*128 + threadIdx.x;
    int i0 = 2*t, i1 = i0 + 1;
    if (i0 >= cnt) return;
    bool has1 = i1 < cnt;
    int S = 1 << lg, M = (1 << (3*lg)) - 1;
    int site0 = g_int[loff + i0];
    int site1 = has1 ? g_int[loff + i1] : site0;
    int b0 = site0 >> (3*lg), r0 = site0 & M;
    int z0 = r0 >> (2*lg), y0 = (r0 >> lg) & (S-1), x0 = r0 & (S-1);
    int b1 = site1 >> (3*lg), r1 = site1 & M;
    int z1 = r1 >> (2*lg), y1 = (r1 >> lg) & (S-1), x1 = r1 & (S-1);
    const float4* fin = (const float4*)g_mem + in4;
    ull a0[8], a1[8];
    #pragma unroll
    for (int p = 0; p < 8; p++) { a0[p] = 0ull; a1[p] = 0ull; }
    #pragma unroll 1
    for (int dz = 0; dz < 3; dz++) {
        int zz0 = z0 + dz - 1, zz1 = z1 + dz - 1;
        bool zk0 = (unsigned)zz0 < (unsigned)S;
        bool zk1 = has1 && ((unsigned)zz1 < (unsigned)S);
        int rr0[9], rr1[9];
        #pragma unroll
        for (int dy = 0; dy < 3; dy++)
        #pragma unroll
        for (int dx = 0; dx < 3; dx++) {
            int k = dy*3 + dx;
            int yy0 = y0+dy-1, xx0 = x0+dx-1;
            rr0[k] = -1;
            if (zk0 && (unsigned)yy0 < (unsigned)S && (unsigned)xx0 < (unsigned)S)
                rr0[k] = g_int[ioff + ((b0 << (3*lg)) + (zz0 << (2*lg)) + (yy0 << lg) + xx0)];
            int yy1 = y1+dy-1, xx1 = x1+dx-1;
            rr1[k] = -1;
            if (zk1 && (unsigned)yy1 < (unsigned)S && (unsigned)xx1 < (unsigned)S)
                rr1[k] = g_int[ioff + ((b1 << (3*lg)) + (zz1 << (2*lg)) + (yy1 << lg) + xx1)];
        }
        #pragma unroll
        for (int k = 0; k < 9; k++) {
            if (rr0[k] < 0 && rr1[k] < 0) continue;
            float q0[16], q1[16];
            #pragma unroll
            for (int c = 0; c < 16; c++) { q0[c] = 0.f; q1[c] = 0.f; }
            if (rr0[k] >= 0) LOADP(q0, fin, rr0[k]);
            if (rr1[k] >= 0) LOADP(q1, fin, rr1[k]);
            const float* wr = sw + (dz*9 + k)*256;
            #pragma unroll
            for (int ci = 0; ci < 16; ci++) {
                ull v0 = pack2(q0[ci]);
                ull v1 = pack2(q1[ci]);
                const ulonglong2* wp = (const ulonglong2*)(wr + ci*16);
                #pragma unroll
                for (int h = 0; h < 4; h++) {
                    ulonglong2 wv = wp[h];
                    fma2(a0[2*h+0], v0, wv.x); fma2(a0[2*h+1], v0, wv.y);
                    fma2(a1[2*h+0], v1, wv.x); fma2(a1[2*h+1], v1, wv.y);
                }
            }
        }
    }
    float4* fo = (float4*)g_mem + out4;
    STOREP(fo, i0, a0);
    if (has1) { STOREP(fo, i1, a1); }
}

__global__ void __launch_bounds__(128) k_conv4(long in4, long out4,
        const float* __restrict__ w, int ioff, int loff, int cidx, int lg) {
    int cnt = g_cnt[cidx];
    if (blockIdx.x*256 >= cnt) return;
    __shared__ __align__(16) float sw[4096];
    int t = blockIdx.x*128 + threadIdx.x;
    int i0 = 2*t, i1 = i0 + 1;
    bool act0 = i0 < cnt, act1 = i1 < cnt;
    int S = 1 << lg, M = (1 << (3*lg)) - 1;
    int site0 = act0 ? g_int[loff + i0] : 0;
    int site1 = act1 ? g_int[loff + i1] : 0;
    int b0 = site0 >> (3*lg), r0 = site0 & M;
    int z0 = r0 >> (2*lg), y0 = (r0 >> lg) & (S-1), x0 = r0 & (S-1);
    int b1 = site1 >> (3*lg), r1 = site1 & M;
    int z1 = r1 >> (2*lg), y1 = (r1 >> lg) & (S-1), x1 = r1 & (S-1);
    const float4* fin = (const float4*)g_mem + in4;
    ull a0[8], a1[8];
    #pragma unroll
    for (int p = 0; p < 8; p++) { a0[p] = 0ull; a1[p] = 0ull; }
    #pragma unroll 1
    for (int dz = 0; dz < 4; dz++) {
        __syncthreads();
        {
            const float4* ws = (const float4*)(w + dz*4096);
            float4* wd = (float4*)sw;
            for (int i = threadIdx.x; i < 1024; i += 128) wd[i] = ws[i];
        }
        __syncthreads();
        int zz0 = z0 + dz - 1, zz1 = z1 + dz - 1;
        bool zk0 = act0 && ((unsigned)zz0 < (unsigned)S);
        bool zk1 = act1 && ((unsigned)zz1 < (unsigned)S);
        if (!(zk0 | zk1)) continue;
        #pragma unroll 1
        for (int dy = 0; dy < 4; dy++) {
            int yy0 = y0+dy-1, yy1 = y1+dy-1;
            bool yk0 = zk0 && ((unsigned)yy0 < (unsigned)S);
            bool yk1 = zk1 && ((unsigned)yy1 < (unsigned)S);
            if (!(yk0 | yk1)) continue;
            int rr0[4], rr1[4];
            #pragma unroll
            for (int dx = 0; dx < 4; dx++) {
                int xx0 = x0+dx-1, xx1 = x1+dx-1;
                rr0[dx] = -1;
                if (yk0 && (unsigned)xx0 < (unsigned)S)
                    rr0[dx] = g_int[ioff + ((b0 << (3*lg)) + (zz0 << (2*lg)) + (yy0 << lg) + xx0)];
                rr1[dx] = -1;
                if (yk1 && (unsigned)xx1 < (unsigned)S)
                    rr1[dx] = g_int[ioff + ((b1 << (3*lg)) + (zz1 << (2*lg)) + (yy1 << lg) + xx1)];
            }
            #pragma unroll
            for (int dx = 0; dx < 4; dx++) {
                if (rr0[dx] < 0 && rr1[dx] < 0) continue;
                float q0[16], q1[16];
                #pragma unroll
                for (int c = 0; c < 16; c++) { q0[c] = 0.f; q1[c] = 0.f; }
                if (rr0[dx] >= 0) {
                    float4 v = fin[rr0[dx]];
                    if (v.x > 0.f) {
                        q0[0]=v.x; q0[1]=v.y; q0[2]=v.z; q0[3]=v.w;
                        v = fin[NS0+rr0[dx]];   q0[4]=v.x; q0[5]=v.y; q0[6]=v.z; q0[7]=v.w;
                        v = fin[2*NS0+rr0[dx]]; q0[8]=v.x; q0[9]=v.y; q0[10]=v.z; q0[11]=v.w;
                        v = fin[3*NS0+rr0[dx]]; q0[12]=v.x; q0[13]=v.y; q0[14]=v.z; q0[15]=v.w;
                    }
                }
                if (rr1[dx] >= 0) {
                    float4 v = fin[rr1[dx]];
                    if (v.x > 0.f) {
                        q1[0]=v.x; q1[1]=v.y; q1[2]=v.z; q1[3]=v.w;
                        v = fin[NS0+rr1[dx]];   q1[4]=v.x; q1[5]=v.y; q1[6]=v.z; q1[7]=v.w;
                        v = fin[2*NS0+rr1[dx]]; q1[8]=v.x; q1[9]=v.y; q1[10]=v.z; q1[11]=v.w;
                        v = fin[3*NS0+rr1[dx]]; q1[12]=v.x; q1[13]=v.y; q1[14]=v.z; q1[15]=v.w;
                    }
                }
                const float* wr = sw + (dy*4 + dx)*256;
                #pragma unroll
                for (int ci = 0; ci < 16; ci++) {
                    ull v0 = pack2(q0[ci]);
                    ull v1 = pack2(q1[ci]);
                    const ulonglong2* wp = (const ulonglong2*)(wr + ci*16);
                    #pragma unroll
                    for (int h = 0; h < 4; h++) {
                        ulonglong2 wv = wp[h];
                        fma2(a0[2*h+0], v0, wv.x); fma2(a0[2*h+1], v0, wv.y);
                        fma2(a1[2*h+0], v1, wv.x); fma2(a1[2*h+1], v1, wv.y);
                    }
                }
            }
        }
    }
    float4* fo = (float4*)g_mem + out4;
    if (act0) { STOREP(fo, i0, a0); }
    if (act1) { STOREP(fo, i1, a1); }
}

__global__ void __launch_bounds__(128) k_down(long in4, long out4,
        const float* __restrict__ w, int fioff, int loff, int cidx, int lg) {
    int cnt = g_cnt[cidx];
    if (blockIdx.x*256 >= cnt) return;
    __shared__ __align__(16) float sw[2048];
    {
        const float4* ws = (const float4*)w;
        float4* wd = (float4*)sw;
        for (int i = threadIdx.x; i < 512; i += 128) wd[i] = ws[i];
    }
    __syncthreads();
    int t = blockIdx.x*128 + threadIdx.x;
    int i0 = 2*t, i1 = i0 + 1;
    if (i0 >= cnt) return;
    bool has1 = i1 < cnt;
    int S = 1 << lg, M = (1 << (3*lg)) - 1, flg = lg + 1;
    int site0 = g_int[loff + i0];
    int site1 = has1 ? g_int[loff + i1] : site0;
    int b0 = site0 >> (3*lg), r0 = site0 & M;
    int z0 = r0 >> (2*lg), y0 = (r0 >> lg) & (S-1), x0 = r0 & (S-1);
    int b1 = site1 >> (3*lg), r1 = site1 & M;
    int z1 = r1 >> (2*lg), y1 = (r1 >> lg) & (S-1), x1 = r1 & (S-1);
    const float4* fin = (const float4*)g_mem + in4;
    int rr0[8], rr1[8];
    #pragma unroll
    for (int ta = 0; ta < 2; ta++)
    #pragma unroll
    for (int tb = 0; tb < 2; tb++)
    #pragma unroll
    for (int tc = 0; tc < 2; tc++) {
        int k = (ta*2+tb)*2+tc;
        rr0[k] = g_int[fioff + ((b0 << (3*flg)) + ((2*z0+ta) << (2*flg)) + ((2*y0+tb) << flg) + (2*x0+tc))];
        rr1[k] = has1 ? g_int[fioff + ((b1 << (3*flg)) + ((2*z1+ta) << (2*flg)) + ((2*y1+tb) << flg) + (2*x1+tc))] : -1;
    }
    ull a0[8], a1[8];
    #pragma unroll
    for (int p = 0; p < 8; p++) { a0[p] = 0ull; a1[p] = 0ull; }
    #pragma unroll
    for (int k = 0; k < 8; k++) {
        if (rr0[k] < 0 && rr1[k] < 0) continue;
        float q0[16], q1[16];
        #pragma unroll
        for (int c = 0; c < 16; c++) { q0[c] = 0.f; q1[c] = 0.f; }
        if (rr0[k] >= 0) LOADP(q0, fin, rr0[k]);
        if (rr1[k] >= 0) LOADP(q1, fin, rr1[k]);
        const float* wr = sw + k*256;
        #pragma unroll
        for (int ci = 0; ci < 16; ci++) {
            ull v0 = pack2(q0[ci]);
            ull v1 = pack2(q1[ci]);
            const ulonglong2* wp = (const ulonglong2*)(wr + ci*16);
            #pragma unroll
            for (int h = 0; h < 4; h++) {
                ulonglong2 wv = wp[h];
                fma2(a0[2*h+0], v0, wv.x); fma2(a0[2*h+1], v0, wv.y);
                fma2(a1[2*h+0], v1, wv.x); fma2(a1[2*h+1], v1, wv.y);
            }
        }
    }
    float4* fo = (float4*)g_mem + out4;
    STOREP(fo, i0, a0);
    if (has1) { STOREP(fo, i1, a1); }
}

__global__ void k_up(long in4, long out4, const float* __restrict__ w,
                     int cioff, int loff, int cidx, int lg) {
    int cnt = g_cnt[cidx];
    if (blockIdx.x*256 >= cnt) return;
    __shared__ __align__(16) float sw[2048];
    {
        const float4* ws = (const float4*)w;
        float4* wd = (float4*)sw;
        for (int i = threadIdx.x; i < 512; i += 256) wd[i] = ws[i];
    }
    __syncthreads();
    int i = blockIdx.x*256 + threadIdx.x;
    if (i >= cnt) return;
    int S = 1 << lg, M = (1 << (3*lg)) - 1, lgc = lg - 1;
    int site = g_int[loff + i];
    int b = site >> (3*lg), r = site & M;
    int z = r >> (2*lg), y = (r >> lg) & (S-1), x = r & (S-1);
    int pn = (b << (3*lgc)) + ((z>>1) << (2*lgc)) + ((y>>1) << lgc) + (x>>1);
    int rp = g_int[cioff + pn];
    ull a[8];
    #pragma unroll
    for (int p = 0; p < 8; p++) a[p] = 0ull;
    if (rp >= 0) {
        const float4* fin = (const float4*)g_mem + in4;
        float qf[16];
        LOADP(qf, fin, rp);
        int tap = ((1-(z&1))*2 + (1-(y&1)))*2 + (1-(x&1));
        const float* wr = sw + tap*256;
        #pragma unroll
        for (int ci = 0; ci < 16; ci++) {
            ull v = pack2(qf[ci]);
            const ulonglong2* wp = (const ulonglong2*)(wr + ci*16);
            #pragma unroll
            for (int h = 0; h < 4; h++) {
                ulonglong2 wv = wp[h];
                fma2(a[2*h+0], v, wv.x);
                fma2(a[2*h+1], v, wv.y);
            }
        }
    }
    float4* fo = (float4*)g_mem + out4;
    STOREP(fo, i, a);
}

__global__ void k_convout(long in4, float* __restrict__ outp,
                          const float* __restrict__ w) {
    __shared__ float sw[432];
    for (int i = threadIdx.x; i < 432; i += 256) sw[i] = w[i];
    __syncthreads();
    int site = blockIdx.x*256 + threadIdx.x;
    const int lg = 6, S = 64;
    if (g_int[IB0 + site] < 0) { outp[site] = 0.f; return; }
    int b = site >> 18, r = site & 0x3ffff;
    int z = r >> 12, y = (r >> 6) & 63, x = r & 63;
    const float4* fin = (const float4*)g_mem + in4;
    float acc = 0.f;
    #pragma unroll 1
    for (int dz = 0; dz < 3; dz++) {
        int zz = z + dz - 1; if ((unsigned)zz >= (unsigned)S) continue;
        int rr[9];
        #pragma unroll
        for (int dy = 0; dy < 3; dy++)
        #pragma unroll
        for (int dx = 0; dx < 3; dx++) {
            int k = dy*3 + dx;
            int yy = y+dy-1, xx = x+dx-1;
            rr[k] = -1;
            if ((unsigned)yy < (unsigned)S && (unsigned)xx < (unsigned)S)
                rr[k] = g_int[IB0 + ((b << (3*lg)) + (zz << (2*lg)) + (yy << lg) + xx)];
        }
        #pragma unroll
        for (int k = 0; k < 9; k++) {
            if (rr[k] < 0) continue;
            float qf[16];
            LOADP(qf, fin, rr[k]);
            const float* wr = sw + (dz*9 + k)*16;
            #pragma unroll
            for (int c = 0; c < 16; c++) acc = fmaf(qf[c], wr[c], acc);
        }
    }
    outp[site] = acc;
}

__global__ void k_hidden(float* __restrict__ outp, long in4) {
    int site = blockIdx.x*256 + threadIdx.x;
    if (site >= NS3) return;
    int rk = g_int[IA3 + site];
    int b = site >> 9, sp = site & 511;
    const float4* f = (const float4*)g_mem + in4;
    #pragma unroll
    for (int h = 0; h < 4; h++) {
        float4 v = (rk >= 0) ? f[h*NS0 + rk] : make_float4(0.f,0.f,0.f,0.f);
        outp[b*8192 + (4*h+0)*512 + sp] = v.x;
        outp[b*8192 + (4*h+1)*512 + sp] = v.y;
        outp[b*8192 + (4*h+2)*512 + sp] = v.z;
        outp[b*8192 + (4*h+3)*512 + sp] = v.w;
    }
}

// ------------------------------- host --------------------------------------

extern "C" void kernel_launch(void* const* d_in, const int* in_sizes, int n_in,
                              void* d_out, int out_size) {
    const float* data      = (const float*)d_in[0];
    const int*   cid       = (const int*)  d_in[1];
    const float* w_prep    = (const float*)d_in[2];
    const float* enc_gamma = (const float*)d_in[3];
    const float* enc_beta  = (const float*)d_in[4];
    const float* enc_wsub  = (const float*)d_in[5];
    const float* enc_wdown = (const float*)d_in[6];
    const float* dec_gamma = (const float*)d_in[7];
    const float* dec_beta  = (const float*)d_in[8];
    const float* dec_wup   = (const float*)d_in[9];
    const float* dec_wsub3 = (const float*)d_in[10];
    const float* dec_wsub4 = (const float*)d_in[11];
    const float* w_out     = (const float*)d_in[12];
    float* outp = (float*)d_out;
    int npts  = in_sizes[0] / 5;
    int mc0   = npts < NS0 ? npts : NS0;
    (void)n_in; (void)out_size;

    k_zero4<<<1024, 256>>>(0L, NS0/4);
    k_scatter<<<CDIV(npts, 256), 256>>>(data, cid, npts);
    k_count<<<NS0/256, 256>>>(0, 6, 0L, 0);
    k_emit <<<NS0/256, 256>>>(0, 6, 0L, 0, IA0, LA0, CA0);

    k_prep<<<CDIV(mc0, 256), 256>>>(BUF_B, w_prep);

    // encoder 0 (64->32)
    k_bnstats<<<GBN, 256>>>(BUF_B, CA0, enc_gamma + 0, enc_beta + 0);
    k_bnapply<<<CDIV(mc0, 256), 256>>>(BUF_B, CA0);
    k_conv3<<<CDIV(mc0, 256), 128>>>(BUF_B, BUF_A, enc_wsub + 0, IA0, LA0, CA0, 6);
    k_count<<<NS1/256, 256>>>(1, 5, 0L, IA0);
    k_emit <<<NS1/256, 256>>>(1, 5, 0L, IA0, IA1, LA1, CA1);
    k_down<<<CDIV(NS1, 256), 128>>>(BUF_A, BUF_B, enc_wdown + 0, IA0, LA1, CA1, 5);

    // encoder 1 (32->16)
    k_bnstats<<<GBN, 256>>>(BUF_B, CA1, enc_gamma + 16, enc_beta + 16);
    k_bnapply<<<CDIV(NS1, 256), 256>>>(BUF_B, CA1);
    k_conv3<<<CDIV(NS1, 256), 128>>>(BUF_B, BUF_A, enc_wsub + 6912, IA1, LA1, CA1, 5);
    k_count<<<NS2/256, 256>>>(1, 4, 0L, IA1);
    k_emit <<<NS2/256, 256>>>(1, 4, 0L, IA1, IA2, LA2, CA2);
    k_down<<<CDIV(NS2, 256), 128>>>(BUF_A, BUF_B, enc_wdown + 2048, IA1, LA2, CA2, 4);

    // encoder 2 (16->8)
    k_bnstats<<<GBN, 256>>>(BUF_B, CA2, enc_gamma + 32, enc_beta + 32);
    k_bnapply<<<CDIV(NS2, 256), 256>>>(BUF_B, CA2);
    k_conv3<<<CDIV(NS2, 256), 128>>>(BUF_B, BUF_A, enc_wsub + 13824, IA2, LA2, CA2, 4);
    k_count<<<NS3/256, 256>>>(1, 3, 0L, IA2);
    k_emit <<<NS3/256, 256>>>(1, 3, 0L, IA2, IA3, LA3, CA3);
    k_down<<<CDIV(NS3, 256), 128>>>(BUF_A, BUF_B, enc_wdown + 4096, IA2, LA3, CA3, 3);

    k_hidden<<<NS3/256, 256>>>(outp, BUF_B);

    // decoder j=0 (8->16)
    k_bnstats<<<GBN, 256>>>(BUF_B, CA3, dec_gamma + 0, dec_beta + 0);
    k_bnapply<<<CDIV(NS3, 256), 256>>>(BUF_B, CA3);
    k_up<<<CDIV(NS2, 256), 256>>>(BUF_B, BUF_A, dec_wup + 0, IA3, LA2, CA2, 4);
    k_conv3<<<CDIV(NS2, 256), 128>>>(BUF_A, BUF_B, dec_wsub3 + 0, IA2, LA2, CA2, 4);
    k_count<<<NS2/256, 256>>>(2, 4, BUF_B, IA2);
    k_emit <<<NS2/256, 256>>>(2, 4, BUF_B, IA2, IB2, LB2, CB2);
    k_conv4<<<CDIV(NS2, 256), 128>>>(BUF_B, BUF_A, dec_wsub4 + 0, IA2, LB2, CB2, 4);

    // decoder j=1 (16->32)
    k_bnstats<<<GBN, 256>>>(BUF_A, CB2, dec_gamma + 16, dec_beta + 16);
    k_bnapply<<<CDIV(NS2, 256), 256>>>(BUF_A, CB2);
    k_up<<<CDIV(NS1, 256), 256>>>(BUF_A, BUF_B, dec_wup + 2048, IB2, LA1, CA1, 5);
    k_conv3<<<CDIV(NS1, 256), 128>>>(BUF_B, BUF_A, dec_wsub3 + 6912, IA1, LA1, CA1, 5);
    k_count<<<NS1/256, 256>>>(2, 5, BUF_A, IA1);
    k_emit <<<NS1/256, 256>>>(2, 5, BUF_A, IA1, IB1, LB1, CB1);
    k_conv4<<<CDIV(NS1, 256), 128>>>(BUF_A, BUF_B, dec_wsub4 + 16384, IA1, LB1, CB1, 5);

    // decoder j=2 (32->64)
    k_bnstats<<<GBN, 256>>>(BUF_B, CB1, dec_gamma + 32, dec_beta + 32);
    k_bnapply<<<CDIV(NS1, 256), 256>>>(BUF_B, CB1);
    k_up<<<CDIV(mc0, 256), 256>>>(BUF_B, BUF_A, dec_wup + 4096, IB1, LA0, CA0, 6);
    k_conv3<<<CDIV(mc0, 256), 128>>>(BUF_A, BUF_B, dec_wsub3 + 13824, IA0, LA0, CA0, 6);
    k_count<<<NS0/256, 256>>>(2, 6, BUF_B, IA0);
    k_emit <<<NS0/256, 256>>>(2, 6, BUF_B, IA0, IB0, LB0, CB0);
    k_conv4<<<CDIV(mc0, 256), 128>>>(BUF_B, BUF_A, dec_wsub4 + 32768, IA0, LB0, CB0, 6);

    k_convout<<<NS0/256, 256>>>(BUF_A, outp + 16*NS3, w_out);
}